// round 9
// baseline (speedup 1.0000x reference)
#include <cuda_runtime.h>
#include <cuda_bf16.h>

// Pendulum RK4 trajectory, N=200000, T=100. out[N][T][2] fp32.
// R2: 297us  scalar strided stores (L1tex wavefront bound, issue 9.8%)
// R4: 46.9us smem-staged warp-transpose float4 stores (issue 77.9%, ~65 slot/step)
// R5: 49.2us f32x2 packing FAILED (pack/unpack MOVs)
// R8: 39.1us full 16-step unroll + LDS.128 dt-triples, BUT regs 30->64,
//     occ 38.7%, issue 65.5% — unroll win partially eaten by occupancy loss.
// R9: unroll 8 + __launch_bounds__(256,5) to cap regs ~51 and restore
//     5 blocks/SM (40 warps). Flush granularity unchanged (16 slots).

#define PEND_T 100
#define PEND_G 10.0f
#define ROWF2  18           // padded particle row in float2 (144B = 9*16B)
#define NWARPS 8

__device__ __forceinline__ void rk4_step(float& theta, float& omega,
                                         float coef, float4 d)
{
    const float dt = d.x, dt3 = d.y, dt8 = d.z;
    const float third = 1.0f / 3.0f;

    const float k1t = omega;
    const float k1w = coef * __sinf(theta);

    const float y2t = fmaf(dt3, k1t, theta);
    const float y2w = fmaf(dt3, k1w, omega);
    const float k2t = y2w;
    const float k2w = coef * __sinf(y2t);

    const float e3t = fmaf(-third, k1t, k2t);      // k2 - k1/3
    const float e3w = fmaf(-third, k1w, k2w);
    const float y3t = fmaf(dt, e3t, theta);
    const float y3w = fmaf(dt, e3w, omega);
    const float k3t = y3w;
    const float k3w = coef * __sinf(y3t);

    const float e4t = (k1t - k2t) + k3t;           // k1 - k2 + k3
    const float e4w = (k1w - k2w) + k3w;
    const float y4t = fmaf(dt, e4t, theta);
    const float y4w = fmaf(dt, e4w, omega);
    const float k4t = y4w;
    const float k4w = coef * __sinf(y4t);

    const float st = fmaf(3.0f, k2t + k3t, k1t) + k4t;   // k1+3(k2+k3)+k4
    const float sw = fmaf(3.0f, k2w + k3w, k1w) + k4w;
    theta = fmaf(dt8, st, theta);
    omega = fmaf(dt8, sw, omega);
}

// Flush one 16-slot chunk: 8 float4 per particle, 8 lanes per particle,
// fully coalesced STG.128 covering whole 128B lines.
__device__ __forceinline__ void flush16(const float2 (* __restrict__ mybuf)[ROWF2],
                                        float4* __restrict__ out4,
                                        size_t rowbase, int lane, int base)
{
    __syncwarp();
    #pragma unroll
    for (int j = 0; j < 8; j++) {
        const int idx = j * 32 + lane;
        const int p   = idx >> 3;          // particle within warp
        const int s4  = idx & 7;           // float4 slot within chunk
        const float4 v = *reinterpret_cast<const float4*>(&mybuf[p][s4 * 2]);
        out4[rowbase + (size_t)p * (PEND_T / 2) + (base >> 1) + s4] = v;
    }
    __syncwarp();
}

__global__ __launch_bounds__(256, 5) void pendulum_rk4_kernel(
    const float* __restrict__ t,
    const float* __restrict__ z0,
    const float* __restrict__ params,
    float* __restrict__ out,
    int n)
{
    __shared__ __align__(16) float4 sdt4[PEND_T - 1];   // {dt, dt/3, dt/8, -}
    __shared__ __align__(16) float2 buf[NWARPS][32][ROWF2];

    for (int j = threadIdx.x; j < PEND_T - 1; j += blockDim.x) {
        const float d = t[j + 1] - t[j];
        sdt4[j] = make_float4(d, d * (1.0f / 3.0f), d * 0.125f, 0.0f);
    }
    __syncthreads();

    const int warp = threadIdx.x >> 5;
    const int lane = threadIdx.x & 31;
    const int warpbase = blockIdx.x * blockDim.x + warp * 32;
    if (warpbase >= n) return;            // n multiple of 32: whole warps only

    float2 (* __restrict__ mybuf)[ROWF2] = buf[warp];

    const int i = warpbase + lane;
    const float2 z = reinterpret_cast<const float2*>(z0)[i];
    float theta = z.x;
    float omega = z.y;
    const float coef = -(PEND_G / params[i]);

    float4* __restrict__ out4 = reinterpret_cast<float4*>(out);
    const size_t rowbase = (size_t)warpbase * (PEND_T / 2);   // 50 float4/row

    // ---- chunk 0: slot 0 (initial state) + steps 1..15 ----
    mybuf[lane][0] = make_float2(theta, omega);
    #pragma unroll 8
    for (int k = 1; k < 16; k++) {
        rk4_step(theta, omega, coef, sdt4[k - 1]);
        mybuf[lane][k] = make_float2(theta, omega);
    }
    flush16(mybuf, out4, rowbase, lane, 0);

    // ---- chunks 1..5: 16 steps each (outer loop rolled for I-cache) ----
    #pragma unroll 1
    for (int c = 1; c < 6; c++) {
        const int base = c * 16;
        #pragma unroll 8
        for (int k = 0; k < 16; k++) {
            rk4_step(theta, omega, coef, sdt4[base - 1 + k]);
            mybuf[lane][k] = make_float2(theta, omega);
        }
        flush16(mybuf, out4, rowbase, lane, base);
    }

    // ---- tail: steps 96..99 (4 slots = 2 float4 per particle) ----
    #pragma unroll
    for (int k = 0; k < 4; k++) {
        rk4_step(theta, omega, coef, sdt4[95 + k]);
        mybuf[lane][k] = make_float2(theta, omega);
    }
    __syncwarp();
    #pragma unroll
    for (int j = 0; j < 2; j++) {
        const int idx = j * 32 + lane;
        const int p   = idx >> 1;
        const int s4  = idx & 1;
        const float4 v = *reinterpret_cast<const float4*>(&mybuf[p][s4 * 2]);
        out4[rowbase + (size_t)p * (PEND_T / 2) + 48 + s4] = v;
    }
}

extern "C" void kernel_launch(void* const* d_in, const int* in_sizes, int n_in,
                              void* d_out, int out_size)
{
    (void)n_in; (void)out_size;
    // d_in[0] = mini_batch (unused), d_in[1] = t, d_in[2] = z0, d_in[3] = params
    const float* t      = (const float*)d_in[1];
    const float* z0     = (const float*)d_in[2];
    const float* params = (const float*)d_in[3];
    float* out          = (float*)d_out;

    const int n = in_sizes[3];
    const int threads = 256;
    const int blocks  = (n + threads - 1) / threads;
    pendulum_rk4_kernel<<<blocks, threads>>>(t, z0, params, out, n);
}